// round 10
// baseline (speedup 1.0000x reference)
#include <cuda_runtime.h>
#include <cuda_bf16.h>
#include <math.h>
#include <stdint.h>

// Problem constants (fixed shapes)
#define NB 2
#define NS 2048
#define ND 4096
#define NH 32
#define NHD 128
#define NAL 10

// ---------------------------------------------------------------------------
// Scratch (__device__ globals — allocation-free rule)
// ---------------------------------------------------------------------------
static __device__ __align__(256) float g_Q[(size_t)NB * NS * ND];
static __device__ __align__(256) float g_K[(size_t)NB * NS * ND];
static __device__ __align__(256) float g_AO[(size_t)NB * NS * ND];
static __device__ __align__(256) float g_scores[(size_t)NB * NH * NS * NS]; // 1 GB
static __device__ float g_ak[NAL * ND];
static __device__ float g_av[NAL * ND];

static __device__ __align__(256) __nv_bfloat16 g_xh[(size_t)NB * NS * ND];
static __device__ __align__(256) __nv_bfloat16 g_xl[(size_t)NB * NS * ND];
static __device__ __align__(256) __nv_bfloat16 g_Qh[(size_t)NB * NS * ND];
static __device__ __align__(256) __nv_bfloat16 g_Ql[(size_t)NB * NS * ND];
static __device__ __align__(256) __nv_bfloat16 g_Kh[(size_t)NB * NS * ND];
static __device__ __align__(256) __nv_bfloat16 g_Kl[(size_t)NB * NS * ND];
static __device__ __align__(256) __nv_bfloat16 g_Vth[(size_t)NB * NS * ND]; // V^T: [b][h][d][s]
static __device__ __align__(256) __nv_bfloat16 g_Vtl[(size_t)NB * NS * ND];
static __device__ __align__(256) __nv_bfloat16 g_Ph[(size_t)NB * NH * NS * NS];
static __device__ __align__(256) __nv_bfloat16 g_Pl[(size_t)NB * NH * NS * NS];
static __device__ __align__(256) __nv_bfloat16 g_AOh[(size_t)NB * NS * ND];
static __device__ __align__(256) __nv_bfloat16 g_AOl[(size_t)NB * NS * ND];
static __device__ __align__(256) __nv_bfloat16 g_wqh[(size_t)ND * ND];
static __device__ __align__(256) __nv_bfloat16 g_wql[(size_t)ND * ND];
static __device__ __align__(256) __nv_bfloat16 g_wkh[(size_t)ND * ND];
static __device__ __align__(256) __nv_bfloat16 g_wkl[(size_t)ND * ND];
static __device__ __align__(256) __nv_bfloat16 g_wvh[(size_t)ND * ND];
static __device__ __align__(256) __nv_bfloat16 g_wvl[(size_t)ND * ND];
static __device__ __align__(256) __nv_bfloat16 g_woh[(size_t)ND * ND];
static __device__ __align__(256) __nv_bfloat16 g_wol[(size_t)ND * ND];

// ---------------------------------------------------------------------------
// Helpers
// ---------------------------------------------------------------------------
__device__ __forceinline__ void split2(float v, __nv_bfloat16& h, __nv_bfloat16& l) {
    h = __float2bfloat16(v);
    l = __float2bfloat16(v - __bfloat162float(h));
}
__device__ __forceinline__ void cpasync16(uint32_t dst, const void* src) {
    asm volatile("cp.async.cg.shared.global [%0], [%1], 16;\n" :: "r"(dst), "l"(src));
}
__device__ __forceinline__ void cp_commit() {
    asm volatile("cp.async.commit_group;\n" ::: "memory");
}
__device__ __forceinline__ void cp_wait1() {
    asm volatile("cp.async.wait_group 1;\n" ::: "memory");
}
__device__ __forceinline__ void ldsm4(uint32_t* r, uint32_t addr) {
    asm volatile("ldmatrix.sync.aligned.m8n8.x4.shared.b16 {%0,%1,%2,%3}, [%4];\n"
                 : "=r"(r[0]), "=r"(r[1]), "=r"(r[2]), "=r"(r[3]) : "r"(addr));
}
__device__ __forceinline__ void mma16816(float* c, const uint32_t* a, const uint32_t* b) {
    asm volatile(
        "mma.sync.aligned.m16n8k16.row.col.f32.bf16.bf16.f32 "
        "{%0,%1,%2,%3},{%4,%5,%6,%7},{%8,%9},{%0,%1,%2,%3};\n"
        : "+f"(c[0]), "+f"(c[1]), "+f"(c[2]), "+f"(c[3])
        : "r"(a[0]), "r"(a[1]), "r"(a[2]), "r"(a[3]), "r"(b[0]), "r"(b[1]));
}

// ---------------------------------------------------------------------------
// Split-bf16 tensor-core GEMM.  C[m][n] = sum_k A[m][k]*B[n][k]
// CTA tile 128x128, 8 warps (2x4) of 64x32, BK=16,
// 3-stage cp.async pipeline (wait_group 1), ONE __syncthreads per k-iter.
// 3 bf16 MMA passes: Ahi*Bhi + Ahi*Blo + Alo*Bhi (fp32 accum).
// SMEM: 3 stages x 16KB = 48KB static.
// Stage layout (bytes): Ahi[0,4K) Alo[4K,8K) Bhi[8K,12K) Blo[12K,16K).
// EPI 0: C fp32.  EPI 1: C = acc*alpha + mask.  EPI 2: V^T hi/lo split write.
// ---------------------------------------------------------------------------
template <int EPI>
__global__ __launch_bounds__(256) void mma_gemm(
    const __nv_bfloat16* __restrict__ Ah, const __nv_bfloat16* __restrict__ Al,
    const __nv_bfloat16* __restrict__ Bh, const __nv_bfloat16* __restrict__ Bl,
    float* __restrict__ C,
    int K, int lda, int ldb, int ldc, int Hdiv,
    long long sAb, long long sAh_, long long sBb, long long sBh_,
    long long sCb, long long sCh_,
    float alpha, const float* __restrict__ mask,
    __nv_bfloat16* __restrict__ Chi, __nv_bfloat16* __restrict__ Clo)
{
    __shared__ __align__(16) __nv_bfloat16 sm[24576];   // 49152 bytes = 3 x 16KB

    const int t = threadIdx.x;
    const int lane = t & 31;
    const int wid = t >> 5;
    const int warp_m = wid >> 2;   // 0..1
    const int warp_n = wid & 3;    // 0..3

    const int z = blockIdx.z;
    const int zb = z / Hdiv;
    const int zh = z % Hdiv;
    const __nv_bfloat16* pAh = Ah + zb * sAb + zh * sAh_;
    const __nv_bfloat16* pAl = Al + zb * sAb + zh * sAh_;
    const __nv_bfloat16* pBh = Bh + zb * sBb + zh * sBh_;
    const __nv_bfloat16* pBl = Bl + zb * sBb + zh * sBh_;
    float* pC = C + zb * sCb + zh * sCh_;

    const int bm = blockIdx.y * 128;
    const int bn = blockIdx.x * 128;

    // Loader: 256 threads -> 128 rows x 2 halves of 8 bf16 (16B)
    const int lrow = t >> 1;
    const int lhalf = (t & 1) * 8;
    const __nv_bfloat16* gAh = pAh + (long long)(bm + lrow) * lda + lhalf;
    const __nv_bfloat16* gAl = pAl + (long long)(bm + lrow) * lda + lhalf;
    const __nv_bfloat16* gBh = pBh + (long long)(bn + lrow) * ldb + lhalf;
    const __nv_bfloat16* gBl = pBl + (long long)(bn + lrow) * ldb + lhalf;

    const uint32_t smem0 = (uint32_t)__cvta_generic_to_shared(sm);
    const uint32_t ldst = (uint32_t)((lrow * 16 + lhalf) * 2);

    // ldmatrix per-lane offsets (row stride 32B)
    const uint32_t aoff = (uint32_t)((lane & 15) * 32 + (lane >> 4) * 16);
    const int rB = (lane & 7) | ((lane & 16) >> 1);
    const uint32_t boff = (uint32_t)(rB * 32 + (lane & 8) * 2);

    const int T = K / 16;

    // stage loader (stage s -> buffer s%3); always commits for group alignment
    auto load_stage = [&](int s) {
        if (s < T) {
            const int kk = s * 16;
            const uint32_t sb = smem0 + (uint32_t)((s % 3) * 16384);
            cpasync16(sb + ldst, gAh + kk);
            cpasync16(sb + 4096 + ldst, gAl + kk);
            cpasync16(sb + 8192 + ldst, gBh + kk);
            cpasync16(sb + 12288 + ldst, gBl + kk);
        }
        cp_commit();
    };

    float c[4][4][4];
#pragma unroll
    for (int i = 0; i < 4; i++)
#pragma unroll
        for (int j = 0; j < 4; j++)
#pragma unroll
            for (int r = 0; r < 4; r++) c[i][j][r] = 0.0f;

    load_stage(0);
    load_stage(1);

    for (int s = 0; s < T; s++) {
        cp_wait1();          // stage s resident (stage s+1 may be in flight)
        __syncthreads();     // also proves all warps done READING buffer (s+2)%3
        load_stage(s + 2);   // overwrite buffer (s+2)%3 == (s-1)%3

        const uint32_t sb = smem0 + (uint32_t)((s % 3) * 16384);
        const uint32_t aH = sb + (uint32_t)(warp_m * 2048) + aoff;
        const uint32_t aL = aH + 4096;
        const uint32_t bH = sb + 8192 + (uint32_t)(warp_n * 1024) + boff;
        const uint32_t bL = bH + 4096;

        uint32_t ah[4][4], al_[4][4], bh[2][4], bl[2][4];
#pragma unroll
        for (int mf = 0; mf < 4; mf++) ldsm4(ah[mf], aH + mf * 512);
#pragma unroll
        for (int nb = 0; nb < 2; nb++) ldsm4(bh[nb], bH + nb * 512);

        // pass 1: Ahi * Bhi
#pragma unroll
        for (int mf = 0; mf < 4; mf++)
#pragma unroll
            for (int nf = 0; nf < 4; nf++)
                mma16816(c[mf][nf], ah[mf], &bh[nf >> 1][(nf & 1) * 2]);

#pragma unroll
        for (int nb = 0; nb < 2; nb++) ldsm4(bl[nb], bL + nb * 512);
        // pass 2: Ahi * Blo
#pragma unroll
        for (int mf = 0; mf < 4; mf++)
#pragma unroll
            for (int nf = 0; nf < 4; nf++)
                mma16816(c[mf][nf], ah[mf], &bl[nf >> 1][(nf & 1) * 2]);

#pragma unroll
        for (int mf = 0; mf < 4; mf++) ldsm4(al_[mf], aL + mf * 512);
        // pass 3: Alo * Bhi
#pragma unroll
        for (int mf = 0; mf < 4; mf++)
#pragma unroll
            for (int nf = 0; nf < 4; nf++)
                mma16816(c[mf][nf], al_[mf], &bh[nf >> 1][(nf & 1) * 2]);
        // NOTE: no trailing __syncthreads — the next iteration's barrier
        // (after cp_wait1) provides the read-before-overwrite guarantee.
    }

    // --- epilogue ---
    const int gq = lane >> 2;
    const int tg = lane & 3;
#pragma unroll
    for (int mf = 0; mf < 4; mf++) {
#pragma unroll
        for (int nf = 0; nf < 4; nf++) {
            const int r0 = bm + warp_m * 64 + mf * 16 + gq;
            const int c0 = bn + warp_n * 32 + nf * 8 + tg * 2;
            float* cc = c[mf][nf];
            if (EPI == 0) {
                *(float2*)&pC[(long long)r0 * ldc + c0] = make_float2(cc[0], cc[1]);
                *(float2*)&pC[(long long)(r0 + 8) * ldc + c0] = make_float2(cc[2], cc[3]);
            } else if (EPI == 1) {
                float2 m0 = *(const float2*)&mask[(long long)r0 * NS + c0];
                float2 m1 = *(const float2*)&mask[(long long)(r0 + 8) * NS + c0];
                *(float2*)&pC[(long long)r0 * ldc + c0] =
                    make_float2(cc[0] * alpha + m0.x, cc[1] * alpha + m0.y);
                *(float2*)&pC[(long long)(r0 + 8) * ldc + c0] =
                    make_float2(cc[2] * alpha + m1.x, cc[3] * alpha + m1.y);
            } else { // EPI == 2: V^T hi/lo   Vt[((b*NH+h)*NHD+dc)*NS + s]
#pragma unroll
                for (int q = 0; q < 4; q++) {
                    const int m = r0 + (q >> 1) * 8;
                    const int n = c0 + (q & 1);
                    const int b = m >> 11, sdx = m & 2047;
                    const int h = n >> 7, dc = n & 127;
                    const long long idx =
                        (((long long)(b * NH + h)) * NHD + dc) * NS + sdx;
                    __nv_bfloat16 hb, lb;
                    split2(cc[q], hb, lb);
                    Chi[idx] = hb;
                    Clo[idx] = lb;
                }
            }
        }
    }
}

// ---------------------------------------------------------------------------
// Elementwise fp32 -> bf16 hi/lo split
// ---------------------------------------------------------------------------
__global__ void split_kernel(const float* __restrict__ src,
                             __nv_bfloat16* __restrict__ h,
                             __nv_bfloat16* __restrict__ l, long long n)
{
    long long i = ((long long)blockIdx.x * blockDim.x + threadIdx.x) * 4;
    if (i >= n) return;
    float4 v = *(const float4*)(src + i);
    __nv_bfloat16 hh[4], ll[4];
    split2(v.x, hh[0], ll[0]);
    split2(v.y, hh[1], ll[1]);
    split2(v.z, hh[2], ll[2]);
    split2(v.w, hh[3], ll[3]);
#pragma unroll
    for (int k = 0; k < 4; k++) { h[i + k] = hh[k]; l[i + k] = ll[k]; }
}

// ---------------------------------------------------------------------------
// Weight transpose + split: Wt[n][k] = W[k][n]
// ---------------------------------------------------------------------------
__global__ void wsplit_t_kernel(const float* __restrict__ W,
                                __nv_bfloat16* __restrict__ Th,
                                __nv_bfloat16* __restrict__ Tl)
{
    __shared__ float tile[32][33];
    const int n0 = blockIdx.x * 32, k0 = blockIdx.y * 32;
    const int tx = threadIdx.x, ty = threadIdx.y;
#pragma unroll
    for (int i = 0; i < 4; i++)
        tile[ty + 8 * i][tx] = W[(long long)(k0 + ty + 8 * i) * ND + n0 + tx];
    __syncthreads();
#pragma unroll
    for (int i = 0; i < 4; i++) {
        float v = tile[tx][ty + 8 * i];
        long long o = (long long)(n0 + ty + 8 * i) * ND + k0 + tx;
        __nv_bfloat16 hb, lb;
        split2(v, hb, lb);
        Th[o] = hb;
        Tl[o] = lb;
    }
}

// ---------------------------------------------------------------------------
// RoPE in-place fp32 + bf16 hi/lo outputs
// ---------------------------------------------------------------------------
__global__ void rope_qk_kernel(float* __restrict__ Q, float* __restrict__ K,
                               const float* __restrict__ cosT,
                               const float* __restrict__ sinT,
                               __nv_bfloat16* __restrict__ Qh, __nv_bfloat16* __restrict__ Ql,
                               __nv_bfloat16* __restrict__ Kh, __nv_bfloat16* __restrict__ Kl)
{
    long long idx = (long long)blockIdx.x * blockDim.x + threadIdx.x;
    const long long total = (long long)NB * NS * NH * (NHD / 2);
    if (idx >= total) return;
    int d2 = (int)(idx & (NHD / 2 - 1));
    long long r = idx >> 6;
    int h = (int)(r & (NH - 1));
    r >>= 5;
    int s = (int)(r & (NS - 1));
    int b = (int)(r >> 11);

    float cv = cosT[s * (NHD / 2) + d2];
    float sn = sinT[s * (NHD / 2) + d2];
    long long off = ((((long long)b * NS + s) * NH + h) * NHD) + 2 * d2;

    float2 q = *(float2*)(Q + off);
    float2 k = *(float2*)(K + off);
    float2 qo, ko;
    qo.x = q.x * cv - q.y * sn;
    qo.y = q.x * sn + q.y * cv;
    ko.x = k.x * cv - k.y * sn;
    ko.y = k.x * sn + k.y * cv;
    *(float2*)(Q + off) = qo;
    *(float2*)(K + off) = ko;

    __nv_bfloat16 hb, lb;
    split2(qo.x, hb, lb); Qh[off] = hb; Ql[off] = lb;
    split2(qo.y, hb, lb); Qh[off + 1] = hb; Ql[off + 1] = lb;
    split2(ko.x, hb, lb); Kh[off] = hb; Kl[off] = lb;
    split2(ko.y, hb, lb); Kh[off + 1] = hb; Kl[off + 1] = lb;
}

// ---------------------------------------------------------------------------
// Adapter projections (tiny fp32)
// ---------------------------------------------------------------------------
__global__ void adapter_gemm_kernel(const float* __restrict__ adapter,
                                    const float* __restrict__ Wk,
                                    const float* __restrict__ Wv,
                                    float* __restrict__ ak,
                                    float* __restrict__ av)
{
    const int n = blockIdx.x * 256 + threadIdx.x;
    __shared__ float a_sh[NAL][64];
    float accK[NAL], accV[NAL];
#pragma unroll
    for (int r = 0; r < NAL; r++) { accK[r] = 0.f; accV[r] = 0.f; }

    for (int k0 = 0; k0 < ND; k0 += 64) {
        for (int idx = threadIdx.x; idx < NAL * 64; idx += 256) {
            int r = idx / 64, cix = idx % 64;
            a_sh[r][cix] = adapter[r * ND + k0 + cix];
        }
        __syncthreads();
        for (int kc = 0; kc < 64; kc++) {
            float bk = Wk[(long long)(k0 + kc) * ND + n];
            float bv = Wv[(long long)(k0 + kc) * ND + n];
#pragma unroll
            for (int r = 0; r < NAL; r++) {
                accK[r] = fmaf(a_sh[r][kc], bk, accK[r]);
                accV[r] = fmaf(a_sh[r][kc], bv, accV[r]);
            }
        }
        __syncthreads();
    }
#pragma unroll
    for (int r = 0; r < NAL; r++) {
        ak[r * ND + n] = accK[r];
        av[r * ND + n] = accV[r];
    }
}

// ---------------------------------------------------------------------------
// Row softmax -> bf16 hi/lo P
// ---------------------------------------------------------------------------
__global__ void softmax_rows_kernel(const float* __restrict__ sc,
                                    __nv_bfloat16* __restrict__ ph,
                                    __nv_bfloat16* __restrict__ pl)
{
    long long row = blockIdx.x;
    const float* p = sc + row * (long long)NS;
    const int t = threadIdx.x;

    float v[8];
#pragma unroll
    for (int i = 0; i < 8; i++) v[i] = p[t + i * 256];

    float m = -1e30f;
#pragma unroll
    for (int i = 0; i < 8; i++) m = fmaxf(m, v[i]);

    __shared__ float red[256];
    red[t] = m;
    __syncthreads();
    for (int s = 128; s > 0; s >>= 1) {
        if (t < s) red[t] = fmaxf(red[t], red[t + s]);
        __syncthreads();
    }
    m = red[0];
    __syncthreads();

    float sum = 0.f;
#pragma unroll
    for (int i = 0; i < 8; i++) {
        v[i] = __expf(v[i] - m);
        sum += v[i];
    }
    red[t] = sum;
    __syncthreads();
    for (int s = 128; s > 0; s >>= 1) {
        if (t < s) red[t] += red[t + s];
        __syncthreads();
    }
    const float inv = 1.0f / red[0];

    long long base = row * (long long)NS;
#pragma unroll
    for (int i = 0; i < 8; i++) {
        float pv = v[i] * inv;
        __nv_bfloat16 hb, lb;
        split2(pv, hb, lb);
        ph[base + t + i * 256] = hb;
        pl[base + t + i * 256] = lb;
    }
}

// ---------------------------------------------------------------------------
// Adapter attention add (gated), fp32
// ---------------------------------------------------------------------------
__global__ void adapter_attn_kernel(float* __restrict__ AO,
                                    const float* __restrict__ Q,
                                    const float* __restrict__ ak,
                                    const float* __restrict__ av,
                                    const float* __restrict__ gate)
{
    const int h = blockIdx.y;
    const int b = blockIdx.z;
    const int lane = threadIdx.x & 31;
    const int w = threadIdx.x >> 5;
    const int q = blockIdx.x * 8 + w;
    const float inv_sqrt = 0.08838834764831845f;

    const float* qp = Q + (((long long)(b * NS + q)) * NH + h) * NHD;
    float qv[4];
#pragma unroll
    for (int i = 0; i < 4; i++) qv[i] = qp[lane + 32 * i];

    float sc[NAL];
#pragma unroll
    for (int j = 0; j < NAL; j++) {
        const float* akp = ak + j * ND + h * NHD;
        float s = 0.f;
#pragma unroll
        for (int i = 0; i < 4; i++) s = fmaf(qv[i], akp[lane + 32 * i], s);
#pragma unroll
        for (int off = 16; off > 0; off >>= 1)
            s += __shfl_xor_sync(0xFFFFFFFFu, s, off);
        sc[j] = s * inv_sqrt;
    }

    float m = sc[0];
#pragma unroll
    for (int j = 1; j < NAL; j++) m = fmaxf(m, sc[j]);
    float sum = 0.f;
#pragma unroll
    for (int j = 0; j < NAL; j++) {
        sc[j] = __expf(sc[j] - m);
        sum += sc[j];
    }
    const float g = gate[h] / sum;

    float o[4] = {0.f, 0.f, 0.f, 0.f};
#pragma unroll
    for (int j = 0; j < NAL; j++) {
        const float* avp = av + j * ND + h * NHD;
#pragma unroll
        for (int i = 0; i < 4; i++) o[i] = fmaf(sc[j], avp[lane + 32 * i], o[i]);
    }

    float* aop = AO + (((long long)(b * NS + q)) * NH + h) * NHD;
#pragma unroll
    for (int i = 0; i < 4; i++) aop[lane + 32 * i] += g * o[i];
}

// ---------------------------------------------------------------------------
// Launch sequence
// ---------------------------------------------------------------------------
extern "C" void kernel_launch(void* const* d_in, const int* in_sizes, int n_in,
                              void* d_out, int out_size)
{
    const float* x       = (const float*)d_in[0];
    const float* cosT    = (const float*)d_in[1];
    const float* sinT    = (const float*)d_in[2];
    const float* mask    = (const float*)d_in[3];
    const float* wq      = (const float*)d_in[4];
    const float* wk      = (const float*)d_in[5];
    const float* wv      = (const float*)d_in[6];
    const float* wo      = (const float*)d_in[7];
    const float* gate    = (const float*)d_in[8];
    const float* adapter = (const float*)d_in[9];
    float* out = (float*)d_out;

    float *Qp, *Kp, *AOp, *Sc, *akp, *avp;
    __nv_bfloat16 *xh, *xl, *Qh, *Ql, *Kh, *Kl, *Vth, *Vtl, *Ph, *Pl, *AOh, *AOl;
    __nv_bfloat16 *wqh, *wql, *wkh, *wkl, *wvh, *wvl, *woh, *wol;
    cudaGetSymbolAddress((void**)&Qp, g_Q);
    cudaGetSymbolAddress((void**)&Kp, g_K);
    cudaGetSymbolAddress((void**)&AOp, g_AO);
    cudaGetSymbolAddress((void**)&Sc, g_scores);
    cudaGetSymbolAddress((void**)&akp, g_ak);
    cudaGetSymbolAddress((void**)&avp, g_av);
    cudaGetSymbolAddress((void**)&xh, g_xh);
    cudaGetSymbolAddress((void**)&xl, g_xl);
    cudaGetSymbolAddress((void**)&Qh, g_Qh);
    cudaGetSymbolAddress((void**)&Ql, g_Ql);
    cudaGetSymbolAddress((void**)&Kh, g_Kh);
    cudaGetSymbolAddress((void**)&Kl, g_Kl);
    cudaGetSymbolAddress((void**)&Vth, g_Vth);
    cudaGetSymbolAddress((void**)&Vtl, g_Vtl);
    cudaGetSymbolAddress((void**)&Ph, g_Ph);
    cudaGetSymbolAddress((void**)&Pl, g_Pl);
    cudaGetSymbolAddress((void**)&AOh, g_AOh);
    cudaGetSymbolAddress((void**)&AOl, g_AOl);
    cudaGetSymbolAddress((void**)&wqh, g_wqh);
    cudaGetSymbolAddress((void**)&wql, g_wql);
    cudaGetSymbolAddress((void**)&wkh, g_wkh);
    cudaGetSymbolAddress((void**)&wkl, g_wkl);
    cudaGetSymbolAddress((void**)&wvh, g_wvh);
    cudaGetSymbolAddress((void**)&wvl, g_wvl);
    cudaGetSymbolAddress((void**)&woh, g_woh);
    cudaGetSymbolAddress((void**)&wol, g_wol);

    const float inv_sqrt = 0.08838834764831845f;
    const long long NTOK = (long long)NB * NS;          // 4096
    const long long NELT = NTOK * ND;                   // 16M
    dim3 blk(256);

    // 0. Split x; transpose+split weights
    split_kernel<<<(unsigned)(NELT / 1024), 256>>>(x, xh, xl, NELT);
    {
        dim3 g(ND / 32, ND / 32), b(32, 8);
        wsplit_t_kernel<<<g, b>>>(wq, wqh, wql);
        wsplit_t_kernel<<<g, b>>>(wk, wkh, wkl);
        wsplit_t_kernel<<<g, b>>>(wv, wvh, wvl);
        wsplit_t_kernel<<<g, b>>>(wo, woh, wol);
    }

    // 1-3. Projections (M=4096, N=4096, K=4096)
    {
        dim3 g(ND / 128, (unsigned)(NTOK / 128), 1);
        mma_gemm<0><<<g, blk>>>(xh, xl, wqh, wql, Qp, ND, ND, ND, ND, 1,
                                0, 0, 0, 0, 0, 0, 1.f, nullptr, nullptr, nullptr);
        mma_gemm<0><<<g, blk>>>(xh, xl, wkh, wkl, Kp, ND, ND, ND, ND, 1,
                                0, 0, 0, 0, 0, 0, 1.f, nullptr, nullptr, nullptr);
        mma_gemm<2><<<g, blk>>>(xh, xl, wvh, wvl, nullptr, ND, ND, ND, ND, 1,
                                0, 0, 0, 0, 0, 0, 1.f, nullptr, Vth, Vtl);
    }

    // 4. RoPE
    {
        const long long total = (long long)NB * NS * NH * (NHD / 2);
        rope_qk_kernel<<<(unsigned)((total + 255) / 256), 256>>>(
            Qp, Kp, cosT, sinT, Qh, Ql, Kh, Kl);
    }

    // 5. Adapter projections
    adapter_gemm_kernel<<<ND / 256, 256>>>(adapter, wk, wv, akp, avp);

    // 6. Scores = Q K^T * inv_sqrt + mask  (per (b,h): M=N=2048, K=128)
    {
        dim3 g(NS / 128, NS / 128, NB * NH);
        mma_gemm<1><<<g, blk>>>(
            Qh, Ql, Kh, Kl, Sc, NHD, ND, ND, NS, NH,
            (long long)NS * ND, (long long)NHD,
            (long long)NS * ND, (long long)NHD,
            (long long)NH * NS * NS, (long long)NS * NS,
            inv_sqrt, mask, nullptr, nullptr);
    }

    // 7. Softmax -> bf16 hi/lo P
    softmax_rows_kernel<<<NB * NH * NS, 256>>>(Sc, Ph, Pl);

    // 8. AO = P @ V  (per (b,h): M=2048, N=128, K=2048)
    {
        dim3 g(NHD / 128, NS / 128, NB * NH);
        mma_gemm<0><<<g, blk>>>(
            Ph, Pl, Vth, Vtl, AOp, NS, NS, NS, ND, NH,
            (long long)NH * NS * NS, (long long)NS * NS,
            (long long)NH * NHD * NS, (long long)NHD * NS,
            (long long)NS * ND, (long long)NHD,
            1.f, nullptr, nullptr, nullptr);
    }

    // 9. Adapter attention add
    adapter_attn_kernel<<<dim3(NS / 8, NH, NB), 256>>>(AOp, Qp, akp, avp, gate);

    // 10. Split AO; out = AO @ wo
    split_kernel<<<(unsigned)(NELT / 1024), 256>>>(AOp, AOh, AOl, NELT);
    {
        dim3 g(ND / 128, (unsigned)(NTOK / 128), 1);
        mma_gemm<0><<<g, blk>>>(AOh, AOl, woh, wol, out, ND, ND, ND, ND, 1,
                                0, 0, 0, 0, 0, 0, 1.f, nullptr, nullptr, nullptr);
    }
}

// round 11
// speedup vs baseline: 1.6918x; 1.6918x over previous
#include <cuda_runtime.h>
#include <cuda_bf16.h>
#include <math.h>
#include <stdint.h>

// Problem constants (fixed shapes)
#define NB 2
#define NS 2048
#define ND 4096
#define NH 32
#define NHD 128
#define NAL 10

// ---------------------------------------------------------------------------
// Scratch (__device__ globals — allocation-free rule)
// ---------------------------------------------------------------------------
static __device__ __align__(256) float g_Q[(size_t)NB * NS * ND];
static __device__ __align__(256) float g_K[(size_t)NB * NS * ND];
static __device__ __align__(256) float g_AO[(size_t)NB * NS * ND];
static __device__ __align__(256) float g_scores[(size_t)NB * NH * NS * NS]; // 1 GB
static __device__ float g_ak[NAL * ND];
static __device__ float g_av[NAL * ND];

static __device__ __align__(256) __nv_bfloat16 g_xh[(size_t)NB * NS * ND];
static __device__ __align__(256) __nv_bfloat16 g_xl[(size_t)NB * NS * ND];
static __device__ __align__(256) __nv_bfloat16 g_Qh[(size_t)NB * NS * ND];
static __device__ __align__(256) __nv_bfloat16 g_Ql[(size_t)NB * NS * ND];
static __device__ __align__(256) __nv_bfloat16 g_Kh[(size_t)NB * NS * ND];
static __device__ __align__(256) __nv_bfloat16 g_Kl[(size_t)NB * NS * ND];
static __device__ __align__(256) __nv_bfloat16 g_Vth[(size_t)NB * NS * ND]; // V^T: [b][h][d][s]
static __device__ __align__(256) __nv_bfloat16 g_Vtl[(size_t)NB * NS * ND];
static __device__ __align__(256) __nv_bfloat16 g_Ph[(size_t)NB * NH * NS * NS];
static __device__ __align__(256) __nv_bfloat16 g_Pl[(size_t)NB * NH * NS * NS];
static __device__ __align__(256) __nv_bfloat16 g_AOh[(size_t)NB * NS * ND];
static __device__ __align__(256) __nv_bfloat16 g_AOl[(size_t)NB * NS * ND];
static __device__ __align__(256) __nv_bfloat16 g_wqh[(size_t)ND * ND];
static __device__ __align__(256) __nv_bfloat16 g_wql[(size_t)ND * ND];
static __device__ __align__(256) __nv_bfloat16 g_wkh[(size_t)ND * ND];
static __device__ __align__(256) __nv_bfloat16 g_wkl[(size_t)ND * ND];
static __device__ __align__(256) __nv_bfloat16 g_wvh[(size_t)ND * ND];
static __device__ __align__(256) __nv_bfloat16 g_wvl[(size_t)ND * ND];
static __device__ __align__(256) __nv_bfloat16 g_woh[(size_t)ND * ND];
static __device__ __align__(256) __nv_bfloat16 g_wol[(size_t)ND * ND];

// ---------------------------------------------------------------------------
// Helpers
// ---------------------------------------------------------------------------
__device__ __forceinline__ void split2(float v, __nv_bfloat16& h, __nv_bfloat16& l) {
    h = __float2bfloat16(v);
    l = __float2bfloat16(v - __bfloat162float(h));
}
__device__ __forceinline__ void cpasync16(uint32_t dst, const void* src) {
    asm volatile("cp.async.cg.shared.global [%0], [%1], 16;\n" :: "r"(dst), "l"(src));
}
__device__ __forceinline__ void cp_commit() {
    asm volatile("cp.async.commit_group;\n" ::: "memory");
}
__device__ __forceinline__ void cp_wait0() {
    asm volatile("cp.async.wait_group 0;\n" ::: "memory");
}
__device__ __forceinline__ void ldsm4(uint32_t* r, uint32_t addr) {
    asm volatile("ldmatrix.sync.aligned.m8n8.x4.shared.b16 {%0,%1,%2,%3}, [%4];\n"
                 : "=r"(r[0]), "=r"(r[1]), "=r"(r[2]), "=r"(r[3]) : "r"(addr));
}
__device__ __forceinline__ void mma16816(float* c, const uint32_t* a, const uint32_t* b) {
    asm volatile(
        "mma.sync.aligned.m16n8k16.row.col.f32.bf16.bf16.f32 "
        "{%0,%1,%2,%3},{%4,%5,%6,%7},{%8,%9},{%0,%1,%2,%3};\n"
        : "+f"(c[0]), "+f"(c[1]), "+f"(c[2]), "+f"(c[3])
        : "r"(a[0]), "r"(a[1]), "r"(a[2]), "r"(a[3]), "r"(b[0]), "r"(b[1]));
}

// ---------------------------------------------------------------------------
// Split-bf16 tensor-core GEMM (R5-proven mainloop).
// C[m][n] = sum_k A[m][k]*B[n][k], 128x128 CTA tile, BK=16, 8 warps (2x4)
// of 64x32, 2-stage cp.async pipeline, 3 bf16 MMA passes (fp32 accum).
// EPI 0: C fp32.  EPI 1: C = acc*alpha + mask.  EPI 2: V^T hi/lo split write.
// CAUSAL 0: dense grid (bn=blockIdx.x, bm=blockIdx.y), full K.
// CAUSAL 1: triangular grid — blockIdx.x enumerates lower-tri (bm,bn) pairs.
// CAUSAL 2: dense grid, K capped at (blockIdx.y+1)*128 (PV with causal P).
// ---------------------------------------------------------------------------
template <int EPI, int CAUSAL>
__global__ __launch_bounds__(256) void mma_gemm(
    const __nv_bfloat16* __restrict__ Ah, const __nv_bfloat16* __restrict__ Al,
    const __nv_bfloat16* __restrict__ Bh, const __nv_bfloat16* __restrict__ Bl,
    float* __restrict__ C,
    int K, int lda, int ldb, int ldc, int Hdiv,
    long long sAb, long long sAh_, long long sBb, long long sBh_,
    long long sCb, long long sCh_,
    float alpha, const float* __restrict__ mask,
    __nv_bfloat16* __restrict__ Chi, __nv_bfloat16* __restrict__ Clo)
{
    __shared__ __align__(16) __nv_bfloat16 sm[16384];   // 32 KB (2 stages)

    const int t = threadIdx.x;
    const int lane = t & 31;
    const int wid = t >> 5;
    const int warp_m = wid >> 2;   // 0..1
    const int warp_n = wid & 3;    // 0..3

    const int z = blockIdx.z;
    const int zb = z / Hdiv;
    const int zh = z % Hdiv;
    const __nv_bfloat16* pAh = Ah + zb * sAb + zh * sAh_;
    const __nv_bfloat16* pAl = Al + zb * sAb + zh * sAh_;
    const __nv_bfloat16* pBh = Bh + zb * sBb + zh * sBh_;
    const __nv_bfloat16* pBl = Bl + zb * sBb + zh * sBh_;
    float* pC = C + zb * sCb + zh * sCh_;

    // Block coordinates (triangular decode for CAUSAL==1)
    int bmB, bnB;
    if (CAUSAL == 1) {
        const int x = blockIdx.x;
        int r = (int)((sqrtf(8.0f * (float)x + 1.0f) - 1.0f) * 0.5f);
        while ((r + 1) * (r + 2) / 2 <= x) r++;
        while (r * (r + 1) / 2 > x) r--;
        bmB = r;
        bnB = x - r * (r + 1) / 2;
    } else {
        bmB = blockIdx.y;
        bnB = blockIdx.x;
    }
    const int bm = bmB * 128;
    const int bn = bnB * 128;

    int Keff = K;
    if (CAUSAL == 2) {
        const int cap = (bmB + 1) * 128;
        Keff = (cap < K) ? cap : K;
    }

    // Loader: 256 threads -> 128 rows x 2 halves of 8 bf16 (16B)
    const int lrow = t >> 1;
    const int lhalf = (t & 1) * 8;
    const __nv_bfloat16* gAh = pAh + (long long)(bm + lrow) * lda + lhalf;
    const __nv_bfloat16* gAl = pAl + (long long)(bm + lrow) * lda + lhalf;
    const __nv_bfloat16* gBh = pBh + (long long)(bn + lrow) * ldb + lhalf;
    const __nv_bfloat16* gBl = pBl + (long long)(bn + lrow) * ldb + lhalf;

    const uint32_t smem0 = (uint32_t)__cvta_generic_to_shared(sm);
    const uint32_t ldst = (uint32_t)((lrow * 16 + lhalf) * 2);

    // ldmatrix per-lane offsets (row stride 32B)
    const uint32_t aoff = (uint32_t)((lane & 15) * 32 + (lane >> 4) * 16);
    const int rB = (lane & 7) | ((lane & 16) >> 1);
    const uint32_t boff = (uint32_t)(rB * 32 + (lane & 8) * 2);

    float c[4][4][4];
#pragma unroll
    for (int i = 0; i < 4; i++)
#pragma unroll
        for (int j = 0; j < 4; j++)
#pragma unroll
            for (int r = 0; r < 4; r++) c[i][j][r] = 0.0f;

    const int T = Keff / 16;

    // prefetch stage 0
    {
        uint32_t da = smem0 + ldst;              // buf0, A hi
        cpasync16(da, gAh);
        cpasync16(da + 4096, gAl);               // A lo
        uint32_t db = smem0 + 16384 + ldst;      // buf0, B hi
        cpasync16(db, gBh);
        cpasync16(db + 4096, gBl);
        cp_commit();
    }

    for (int s = 0; s < T; s++) {
        cp_wait0();
        __syncthreads();

        if (s + 1 < T) {
            const int kk = (s + 1) * 16;
            const int buf = (s + 1) & 1;
            uint32_t da = smem0 + (uint32_t)(buf * 8192) + ldst;
            cpasync16(da, gAh + kk);
            cpasync16(da + 4096, gAl + kk);
            uint32_t db = smem0 + 16384 + (uint32_t)(buf * 8192) + ldst;
            cpasync16(db, gBh + kk);
            cpasync16(db + 4096, gBl + kk);
            cp_commit();
        }

        const int buf = s & 1;
        const uint32_t aH = smem0 + (uint32_t)(buf * 8192) + (uint32_t)(warp_m * 2048) + aoff;
        const uint32_t aL = aH + 4096;
        const uint32_t bH = smem0 + 16384 + (uint32_t)(buf * 8192) + (uint32_t)(warp_n * 1024) + boff;
        const uint32_t bL = bH + 4096;

        uint32_t ah[4][4], al_[4][4], bh[2][4], bl[2][4];
#pragma unroll
        for (int mf = 0; mf < 4; mf++) ldsm4(ah[mf], aH + mf * 512);
#pragma unroll
        for (int mf = 0; mf < 4; mf++) ldsm4(al_[mf], aL + mf * 512);
#pragma unroll
        for (int nb = 0; nb < 2; nb++) ldsm4(bh[nb], bH + nb * 512);
#pragma unroll
        for (int nb = 0; nb < 2; nb++) ldsm4(bl[nb], bL + nb * 512);

        // pass 1: Ahi * Bhi
#pragma unroll
        for (int mf = 0; mf < 4; mf++)
#pragma unroll
            for (int nf = 0; nf < 4; nf++)
                mma16816(c[mf][nf], ah[mf], &bh[nf >> 1][(nf & 1) * 2]);
        // pass 2: Ahi * Blo
#pragma unroll
        for (int mf = 0; mf < 4; mf++)
#pragma unroll
            for (int nf = 0; nf < 4; nf++)
                mma16816(c[mf][nf], ah[mf], &bl[nf >> 1][(nf & 1) * 2]);
        // pass 3: Alo * Bhi
#pragma unroll
        for (int mf = 0; mf < 4; mf++)
#pragma unroll
            for (int nf = 0; nf < 4; nf++)
                mma16816(c[mf][nf], al_[mf], &bh[nf >> 1][(nf & 1) * 2]);

        __syncthreads();
    }

    // --- epilogue ---
    const int gq = lane >> 2;
    const int tg = lane & 3;
#pragma unroll
    for (int mf = 0; mf < 4; mf++) {
#pragma unroll
        for (int nf = 0; nf < 4; nf++) {
            const int r0 = bm + warp_m * 64 + mf * 16 + gq;
            const int c0 = bn + warp_n * 32 + nf * 8 + tg * 2;
            float* cc = c[mf][nf];
            if (EPI == 0) {
                *(float2*)&pC[(long long)r0 * ldc + c0] = make_float2(cc[0], cc[1]);
                *(float2*)&pC[(long long)(r0 + 8) * ldc + c0] = make_float2(cc[2], cc[3]);
            } else if (EPI == 1) {
                float2 m0 = *(const float2*)&mask[(long long)r0 * NS + c0];
                float2 m1 = *(const float2*)&mask[(long long)(r0 + 8) * NS + c0];
                *(float2*)&pC[(long long)r0 * ldc + c0] =
                    make_float2(cc[0] * alpha + m0.x, cc[1] * alpha + m0.y);
                *(float2*)&pC[(long long)(r0 + 8) * ldc + c0] =
                    make_float2(cc[2] * alpha + m1.x, cc[3] * alpha + m1.y);
            } else { // EPI == 2: V^T hi/lo   Vt[((b*NH+h)*NHD+dc)*NS + s]
#pragma unroll
                for (int q = 0; q < 4; q++) {
                    const int m = r0 + (q >> 1) * 8;
                    const int n = c0 + (q & 1);
                    const int b = m >> 11, sdx = m & 2047;
                    const int h = n >> 7, dc = n & 127;
                    const long long idx =
                        (((long long)(b * NH + h)) * NHD + dc) * NS + sdx;
                    __nv_bfloat16 hb, lb;
                    split2(cc[q], hb, lb);
                    Chi[idx] = hb;
                    Clo[idx] = lb;
                }
            }
        }
    }
}

// ---------------------------------------------------------------------------
// Elementwise fp32 -> bf16 hi/lo split
// ---------------------------------------------------------------------------
__global__ void split_kernel(const float* __restrict__ src,
                             __nv_bfloat16* __restrict__ h,
                             __nv_bfloat16* __restrict__ l, long long n)
{
    long long i = ((long long)blockIdx.x * blockDim.x + threadIdx.x) * 4;
    if (i >= n) return;
    float4 v = *(const float4*)(src + i);
    __nv_bfloat16 hh[4], ll[4];
    split2(v.x, hh[0], ll[0]);
    split2(v.y, hh[1], ll[1]);
    split2(v.z, hh[2], ll[2]);
    split2(v.w, hh[3], ll[3]);
#pragma unroll
    for (int k = 0; k < 4; k++) { h[i + k] = hh[k]; l[i + k] = ll[k]; }
}

// ---------------------------------------------------------------------------
// Weight transpose + split: Wt[n][k] = W[k][n]
// ---------------------------------------------------------------------------
__global__ void wsplit_t_kernel(const float* __restrict__ W,
                                __nv_bfloat16* __restrict__ Th,
                                __nv_bfloat16* __restrict__ Tl)
{
    __shared__ float tile[32][33];
    const int n0 = blockIdx.x * 32, k0 = blockIdx.y * 32;
    const int tx = threadIdx.x, ty = threadIdx.y;
#pragma unroll
    for (int i = 0; i < 4; i++)
        tile[ty + 8 * i][tx] = W[(long long)(k0 + ty + 8 * i) * ND + n0 + tx];
    __syncthreads();
#pragma unroll
    for (int i = 0; i < 4; i++) {
        float v = tile[tx][ty + 8 * i];
        long long o = (long long)(n0 + ty + 8 * i) * ND + k0 + tx;
        __nv_bfloat16 hb, lb;
        split2(v, hb, lb);
        Th[o] = hb;
        Tl[o] = lb;
    }
}

// ---------------------------------------------------------------------------
// RoPE in-place fp32 + bf16 hi/lo outputs
// ---------------------------------------------------------------------------
__global__ void rope_qk_kernel(float* __restrict__ Q, float* __restrict__ K,
                               const float* __restrict__ cosT,
                               const float* __restrict__ sinT,
                               __nv_bfloat16* __restrict__ Qh, __nv_bfloat16* __restrict__ Ql,
                               __nv_bfloat16* __restrict__ Kh, __nv_bfloat16* __restrict__ Kl)
{
    long long idx = (long long)blockIdx.x * blockDim.x + threadIdx.x;
    const long long total = (long long)NB * NS * NH * (NHD / 2);
    if (idx >= total) return;
    int d2 = (int)(idx & (NHD / 2 - 1));
    long long r = idx >> 6;
    int h = (int)(r & (NH - 1));
    r >>= 5;
    int s = (int)(r & (NS - 1));
    int b = (int)(r >> 11);

    float cv = cosT[s * (NHD / 2) + d2];
    float sn = sinT[s * (NHD / 2) + d2];
    long long off = ((((long long)b * NS + s) * NH + h) * NHD) + 2 * d2;

    float2 q = *(float2*)(Q + off);
    float2 k = *(float2*)(K + off);
    float2 qo, ko;
    qo.x = q.x * cv - q.y * sn;
    qo.y = q.x * sn + q.y * cv;
    ko.x = k.x * cv - k.y * sn;
    ko.y = k.x * sn + k.y * cv;
    *(float2*)(Q + off) = qo;
    *(float2*)(K + off) = ko;

    __nv_bfloat16 hb, lb;
    split2(qo.x, hb, lb); Qh[off] = hb; Ql[off] = lb;
    split2(qo.y, hb, lb); Qh[off + 1] = hb; Ql[off + 1] = lb;
    split2(ko.x, hb, lb); Kh[off] = hb; Kl[off] = lb;
    split2(ko.y, hb, lb); Kh[off + 1] = hb; Kl[off + 1] = lb;
}

// ---------------------------------------------------------------------------
// Adapter projections (tiny fp32)
// ---------------------------------------------------------------------------
__global__ void adapter_gemm_kernel(const float* __restrict__ adapter,
                                    const float* __restrict__ Wk,
                                    const float* __restrict__ Wv,
                                    float* __restrict__ ak,
                                    float* __restrict__ av)
{
    const int n = blockIdx.x * 256 + threadIdx.x;
    __shared__ float a_sh[NAL][64];
    float accK[NAL], accV[NAL];
#pragma unroll
    for (int r = 0; r < NAL; r++) { accK[r] = 0.f; accV[r] = 0.f; }

    for (int k0 = 0; k0 < ND; k0 += 64) {
        for (int idx = threadIdx.x; idx < NAL * 64; idx += 256) {
            int r = idx / 64, cix = idx % 64;
            a_sh[r][cix] = adapter[r * ND + k0 + cix];
        }
        __syncthreads();
        for (int kc = 0; kc < 64; kc++) {
            float bk = Wk[(long long)(k0 + kc) * ND + n];
            float bv = Wv[(long long)(k0 + kc) * ND + n];
#pragma unroll
            for (int r = 0; r < NAL; r++) {
                accK[r] = fmaf(a_sh[r][kc], bk, accK[r]);
                accV[r] = fmaf(a_sh[r][kc], bv, accV[r]);
            }
        }
        __syncthreads();
    }
#pragma unroll
    for (int r = 0; r < NAL; r++) {
        ak[r * ND + n] = accK[r];
        av[r * ND + n] = accV[r];
    }
}

// ---------------------------------------------------------------------------
// Row softmax -> bf16 hi/lo P (causal: only valid prefix of each row).
// Row r valid cols: [0, nv) with nv = (r/128+1)*128; diagonal-block masked
// entries underflow to exactly 0 (same as fp32 reference). Cols >= nv are
// never written and never read (PV caps K at nv).
// ---------------------------------------------------------------------------
__global__ void softmax_rows_kernel(const float* __restrict__ sc,
                                    __nv_bfloat16* __restrict__ ph,
                                    __nv_bfloat16* __restrict__ pl)
{
    long long row = blockIdx.x;
    const int rq = (int)(row & (NS - 1));           // q position within (b,h)
    const int nv = ((rq >> 7) + 1) << 7;            // valid col count
    const float* p = sc + row * (long long)NS;
    const int t = threadIdx.x;

    float v[8];
#pragma unroll
    for (int i = 0; i < 8; i++) {
        const int col = t + i * 256;
        v[i] = (col < nv) ? p[col] : -1e30f;
    }

    float m = -1e30f;
#pragma unroll
    for (int i = 0; i < 8; i++) m = fmaxf(m, v[i]);

    __shared__ float red[256];
    red[t] = m;
    __syncthreads();
    for (int s = 128; s > 0; s >>= 1) {
        if (t < s) red[t] = fmaxf(red[t], red[t + s]);
        __syncthreads();
    }
    m = red[0];
    __syncthreads();

    float sum = 0.f;
#pragma unroll
    for (int i = 0; i < 8; i++) {
        v[i] = __expf(v[i] - m);
        sum += v[i];
    }
    red[t] = sum;
    __syncthreads();
    for (int s = 128; s > 0; s >>= 1) {
        if (t < s) red[t] += red[t + s];
        __syncthreads();
    }
    const float inv = 1.0f / red[0];

    long long base = row * (long long)NS;
#pragma unroll
    for (int i = 0; i < 8; i++) {
        const int col = t + i * 256;
        if (col < nv) {
            float pv = v[i] * inv;
            __nv_bfloat16 hb, lb;
            split2(pv, hb, lb);
            ph[base + col] = hb;
            pl[base + col] = lb;
        }
    }
}

// ---------------------------------------------------------------------------
// Adapter attention add (gated), fp32
// ---------------------------------------------------------------------------
__global__ void adapter_attn_kernel(float* __restrict__ AO,
                                    const float* __restrict__ Q,
                                    const float* __restrict__ ak,
                                    const float* __restrict__ av,
                                    const float* __restrict__ gate)
{
    const int h = blockIdx.y;
    const int b = blockIdx.z;
    const int lane = threadIdx.x & 31;
    const int w = threadIdx.x >> 5;
    const int q = blockIdx.x * 8 + w;
    const float inv_sqrt = 0.08838834764831845f;

    const float* qp = Q + (((long long)(b * NS + q)) * NH + h) * NHD;
    float qv[4];
#pragma unroll
    for (int i = 0; i < 4; i++) qv[i] = qp[lane + 32 * i];

    float sc[NAL];
#pragma unroll
    for (int j = 0; j < NAL; j++) {
        const float* akp = ak + j * ND + h * NHD;
        float s = 0.f;
#pragma unroll
        for (int i = 0; i < 4; i++) s = fmaf(qv[i], akp[lane + 32 * i], s);
#pragma unroll
        for (int off = 16; off > 0; off >>= 1)
            s += __shfl_xor_sync(0xFFFFFFFFu, s, off);
        sc[j] = s * inv_sqrt;
    }

    float m = sc[0];
#pragma unroll
    for (int j = 1; j < NAL; j++) m = fmaxf(m, sc[j]);
    float sum = 0.f;
#pragma unroll
    for (int j = 0; j < NAL; j++) {
        sc[j] = __expf(sc[j] - m);
        sum += sc[j];
    }
    const float g = gate[h] / sum;

    float o[4] = {0.f, 0.f, 0.f, 0.f};
#pragma unroll
    for (int j = 0; j < NAL; j++) {
        const float* avp = av + j * ND + h * NHD;
#pragma unroll
        for (int i = 0; i < 4; i++) o[i] = fmaf(sc[j], avp[lane + 32 * i], o[i]);
    }

    float* aop = AO + (((long long)(b * NS + q)) * NH + h) * NHD;
#pragma unroll
    for (int i = 0; i < 4; i++) aop[lane + 32 * i] += g * o[i];
}

// ---------------------------------------------------------------------------
// Launch sequence
// ---------------------------------------------------------------------------
extern "C" void kernel_launch(void* const* d_in, const int* in_sizes, int n_in,
                              void* d_out, int out_size)
{
    const float* x       = (const float*)d_in[0];
    const float* cosT    = (const float*)d_in[1];
    const float* sinT    = (const float*)d_in[2];
    const float* mask    = (const float*)d_in[3];
    const float* wq      = (const float*)d_in[4];
    const float* wk      = (const float*)d_in[5];
    const float* wv      = (const float*)d_in[6];
    const float* wo      = (const float*)d_in[7];
    const float* gate    = (const float*)d_in[8];
    const float* adapter = (const float*)d_in[9];
    float* out = (float*)d_out;

    float *Qp, *Kp, *AOp, *Sc, *akp, *avp;
    __nv_bfloat16 *xh, *xl, *Qh, *Ql, *Kh, *Kl, *Vth, *Vtl, *Ph, *Pl, *AOh, *AOl;
    __nv_bfloat16 *wqh, *wql, *wkh, *wkl, *wvh, *wvl, *woh, *wol;
    cudaGetSymbolAddress((void**)&Qp, g_Q);
    cudaGetSymbolAddress((void**)&Kp, g_K);
    cudaGetSymbolAddress((void**)&AOp, g_AO);
    cudaGetSymbolAddress((void**)&Sc, g_scores);
    cudaGetSymbolAddress((void**)&akp, g_ak);
    cudaGetSymbolAddress((void**)&avp, g_av);
    cudaGetSymbolAddress((void**)&xh, g_xh);
    cudaGetSymbolAddress((void**)&xl, g_xl);
    cudaGetSymbolAddress((void**)&Qh, g_Qh);
    cudaGetSymbolAddress((void**)&Ql, g_Ql);
    cudaGetSymbolAddress((void**)&Kh, g_Kh);
    cudaGetSymbolAddress((void**)&Kl, g_Kl);
    cudaGetSymbolAddress((void**)&Vth, g_Vth);
    cudaGetSymbolAddress((void**)&Vtl, g_Vtl);
    cudaGetSymbolAddress((void**)&Ph, g_Ph);
    cudaGetSymbolAddress((void**)&Pl, g_Pl);
    cudaGetSymbolAddress((void**)&AOh, g_AOh);
    cudaGetSymbolAddress((void**)&AOl, g_AOl);
    cudaGetSymbolAddress((void**)&wqh, g_wqh);
    cudaGetSymbolAddress((void**)&wql, g_wql);
    cudaGetSymbolAddress((void**)&wkh, g_wkh);
    cudaGetSymbolAddress((void**)&wkl, g_wkl);
    cudaGetSymbolAddress((void**)&wvh, g_wvh);
    cudaGetSymbolAddress((void**)&wvl, g_wvl);
    cudaGetSymbolAddress((void**)&woh, g_woh);
    cudaGetSymbolAddress((void**)&wol, g_wol);

    const float inv_sqrt = 0.08838834764831845f;
    const long long NTOK = (long long)NB * NS;          // 4096
    const long long NELT = NTOK * ND;                   // 16M
    dim3 blk(256);

    // 0. Split x; transpose+split weights
    split_kernel<<<(unsigned)(NELT / 1024), 256>>>(x, xh, xl, NELT);
    {
        dim3 g(ND / 32, ND / 32), b(32, 8);
        wsplit_t_kernel<<<g, b>>>(wq, wqh, wql);
        wsplit_t_kernel<<<g, b>>>(wk, wkh, wkl);
        wsplit_t_kernel<<<g, b>>>(wv, wvh, wvl);
        wsplit_t_kernel<<<g, b>>>(wo, woh, wol);
    }

    // 1-3. Projections (M=4096, N=4096, K=4096)
    {
        dim3 g(ND / 128, (unsigned)(NTOK / 128), 1);
        mma_gemm<0, 0><<<g, blk>>>(xh, xl, wqh, wql, Qp, ND, ND, ND, ND, 1,
                                   0, 0, 0, 0, 0, 0, 1.f, nullptr, nullptr, nullptr);
        mma_gemm<0, 0><<<g, blk>>>(xh, xl, wkh, wkl, Kp, ND, ND, ND, ND, 1,
                                   0, 0, 0, 0, 0, 0, 1.f, nullptr, nullptr, nullptr);
        mma_gemm<2, 0><<<g, blk>>>(xh, xl, wvh, wvl, nullptr, ND, ND, ND, ND, 1,
                                   0, 0, 0, 0, 0, 0, 1.f, nullptr, Vth, Vtl);
    }

    // 4. RoPE
    {
        const long long total = (long long)NB * NS * NH * (NHD / 2);
        rope_qk_kernel<<<(unsigned)((total + 255) / 256), 256>>>(
            Qp, Kp, cosT, sinT, Qh, Ql, Kh, Kl);
    }

    // 5. Adapter projections
    adapter_gemm_kernel<<<ND / 256, 256>>>(adapter, wk, wv, akp, avp);

    // 6. Scores = Q K^T * inv_sqrt + mask — lower-triangular blocks only.
    //    16 row-blocks -> 16*17/2 = 136 (bm,bn) pairs.
    {
        dim3 g(136, 1, NB * NH);
        mma_gemm<1, 1><<<g, blk>>>(
            Qh, Ql, Kh, Kl, Sc, NHD, ND, ND, NS, NH,
            (long long)NS * ND, (long long)NHD,
            (long long)NS * ND, (long long)NHD,
            (long long)NH * NS * NS, (long long)NS * NS,
            inv_sqrt, mask, nullptr, nullptr);
    }

    // 7. Softmax (causal prefix) -> bf16 hi/lo P
    softmax_rows_kernel<<<NB * NH * NS, 256>>>(Sc, Ph, Pl);

    // 8. AO = P @ V  (per (b,h): M=2048, N=128; K capped causally per q-block)
    {
        dim3 g(NHD / 128, NS / 128, NB * NH);
        mma_gemm<0, 2><<<g, blk>>>(
            Ph, Pl, Vth, Vtl, AOp, NS, NS, NS, ND, NH,
            (long long)NH * NS * NS, (long long)NS * NS,
            (long long)NH * NHD * NS, (long long)NHD * NS,
            (long long)NS * ND, (long long)NHD,
            1.f, nullptr, nullptr, nullptr);
    }

    // 9. Adapter attention add
    adapter_attn_kernel<<<dim3(NS / 8, NH, NB), 256>>>(AOp, Qp, akp, avp, gate);

    // 10. Split AO; out = AO @ wo
    split_kernel<<<(unsigned)(NELT / 1024), 256>>>(AOp, AOh, AOl, NELT);
    {
        dim3 g(ND / 128, (unsigned)(NTOK / 128), 1);
        mma_gemm<0, 0><<<g, blk>>>(AOh, AOl, woh, wol, out, ND, ND, ND, ND, 1,
                                   0, 0, 0, 0, 0, 0, 1.f, nullptr, nullptr, nullptr);
    }
}

// round 12
// speedup vs baseline: 1.8147x; 1.0727x over previous
#include <cuda_runtime.h>
#include <cuda_bf16.h>
#include <math.h>
#include <stdint.h>

// Problem constants (fixed shapes)
#define NB 2
#define NS 2048
#define ND 4096
#define NH 32
#define NHD 128
#define NAL 10

// ---------------------------------------------------------------------------
// Scratch (__device__ globals — allocation-free rule)
// ---------------------------------------------------------------------------
static __device__ __align__(256) float g_Q[(size_t)NB * NS * ND];   // post-rope fp32 Q
static __device__ __align__(256) float g_AO[(size_t)NB * NS * ND];
static __device__ __align__(256) float g_scores[(size_t)NB * NH * NS * NS]; // 1 GB
static __device__ float g_ak[NAL * ND];
static __device__ float g_av[NAL * ND];

static __device__ __align__(256) __nv_bfloat16 g_xh[(size_t)NB * NS * ND];
static __device__ __align__(256) __nv_bfloat16 g_xl[(size_t)NB * NS * ND];
static __device__ __align__(256) __nv_bfloat16 g_Qh[(size_t)NB * NS * ND];
static __device__ __align__(256) __nv_bfloat16 g_Ql[(size_t)NB * NS * ND];
static __device__ __align__(256) __nv_bfloat16 g_Kh[(size_t)NB * NS * ND];
static __device__ __align__(256) __nv_bfloat16 g_Kl[(size_t)NB * NS * ND];
static __device__ __align__(256) __nv_bfloat16 g_Vth[(size_t)NB * NS * ND]; // V^T: [b][h][d][s]
static __device__ __align__(256) __nv_bfloat16 g_Vtl[(size_t)NB * NS * ND];
static __device__ __align__(256) __nv_bfloat16 g_Ph[(size_t)NB * NH * NS * NS];
static __device__ __align__(256) __nv_bfloat16 g_Pl[(size_t)NB * NH * NS * NS];
static __device__ __align__(256) __nv_bfloat16 g_AOh[(size_t)NB * NS * ND];
static __device__ __align__(256) __nv_bfloat16 g_AOl[(size_t)NB * NS * ND];
static __device__ __align__(256) __nv_bfloat16 g_wqh[(size_t)ND * ND];
static __device__ __align__(256) __nv_bfloat16 g_wql[(size_t)ND * ND];
static __device__ __align__(256) __nv_bfloat16 g_wkh[(size_t)ND * ND];
static __device__ __align__(256) __nv_bfloat16 g_wkl[(size_t)ND * ND];
static __device__ __align__(256) __nv_bfloat16 g_wvh[(size_t)ND * ND];
static __device__ __align__(256) __nv_bfloat16 g_wvl[(size_t)ND * ND];
static __device__ __align__(256) __nv_bfloat16 g_woh[(size_t)ND * ND];
static __device__ __align__(256) __nv_bfloat16 g_wol[(size_t)ND * ND];

// ---------------------------------------------------------------------------
// Helpers
// ---------------------------------------------------------------------------
__device__ __forceinline__ void split2(float v, __nv_bfloat16& h, __nv_bfloat16& l) {
    h = __float2bfloat16(v);
    l = __float2bfloat16(v - __bfloat162float(h));
}
__device__ __forceinline__ void cpasync16(uint32_t dst, const void* src) {
    asm volatile("cp.async.cg.shared.global [%0], [%1], 16;\n" :: "r"(dst), "l"(src));
}
__device__ __forceinline__ void cp_commit() {
    asm volatile("cp.async.commit_group;\n" ::: "memory");
}
__device__ __forceinline__ void cp_wait0() {
    asm volatile("cp.async.wait_group 0;\n" ::: "memory");
}
__device__ __forceinline__ void ldsm4(uint32_t* r, uint32_t addr) {
    asm volatile("ldmatrix.sync.aligned.m8n8.x4.shared.b16 {%0,%1,%2,%3}, [%4];\n"
                 : "=r"(r[0]), "=r"(r[1]), "=r"(r[2]), "=r"(r[3]) : "r"(addr));
}
__device__ __forceinline__ void mma16816(float* c, const uint32_t* a, const uint32_t* b) {
    asm volatile(
        "mma.sync.aligned.m16n8k16.row.col.f32.bf16.bf16.f32 "
        "{%0,%1,%2,%3},{%4,%5,%6,%7},{%8,%9},{%0,%1,%2,%3};\n"
        : "+f"(c[0]), "+f"(c[1]), "+f"(c[2]), "+f"(c[3])
        : "r"(a[0]), "r"(a[1]), "r"(a[2]), "r"(a[3]), "r"(b[0]), "r"(b[1]));
}

// ---------------------------------------------------------------------------
// Split-bf16 tensor-core GEMM (R5-proven mainloop).
// C[m][n] = sum_k A[m][k]*B[n][k], 128x128 CTA tile, BK=16, 8 warps (2x4)
// of 64x32, 2-stage cp.async pipeline, 3 bf16 MMA passes (fp32 accum).
// EPI 0: C fp32.
// EPI 1: C = acc*alpha + analytic causal mask ((col>row)?-1e9:0).
// EPI 2: V^T hi/lo split write.
// EPI 3: RoPE applied, write fp32 C AND hi/lo split (Q projection).
// EPI 4: RoPE applied, write hi/lo split only (K projection).
// CAUSAL 0: dense grid, full K.
// CAUSAL 1: triangular grid — blockIdx.x enumerates lower-tri (bm,bn) pairs.
// CAUSAL 2: dense grid, K capped at (blockIdx.y+1)*128 (PV with causal P).
// ---------------------------------------------------------------------------
template <int EPI, int CAUSAL>
__global__ __launch_bounds__(256, 2) void mma_gemm(
    const __nv_bfloat16* __restrict__ Ah, const __nv_bfloat16* __restrict__ Al,
    const __nv_bfloat16* __restrict__ Bh, const __nv_bfloat16* __restrict__ Bl,
    float* __restrict__ C,
    int K, int lda, int ldb, int ldc, int Hdiv,
    long long sAb, long long sAh_, long long sBb, long long sBh_,
    long long sCb, long long sCh_,
    float alpha, const float* __restrict__ cosT, const float* __restrict__ sinT,
    __nv_bfloat16* __restrict__ Chi, __nv_bfloat16* __restrict__ Clo)
{
    __shared__ __align__(16) __nv_bfloat16 sm[16384];   // 32 KB (2 stages)

    const int t = threadIdx.x;
    const int lane = t & 31;
    const int wid = t >> 5;
    const int warp_m = wid >> 2;   // 0..1
    const int warp_n = wid & 3;    // 0..3

    const int z = blockIdx.z;
    const int zb = z / Hdiv;
    const int zh = z % Hdiv;
    const __nv_bfloat16* pAh = Ah + zb * sAb + zh * sAh_;
    const __nv_bfloat16* pAl = Al + zb * sAb + zh * sAh_;
    const __nv_bfloat16* pBh = Bh + zb * sBb + zh * sBh_;
    const __nv_bfloat16* pBl = Bl + zb * sBb + zh * sBh_;
    float* pC = C + zb * sCb + zh * sCh_;

    // Block coordinates (triangular decode for CAUSAL==1)
    int bmB, bnB;
    if (CAUSAL == 1) {
        const int x = blockIdx.x;
        int r = (int)((sqrtf(8.0f * (float)x + 1.0f) - 1.0f) * 0.5f);
        while ((r + 1) * (r + 2) / 2 <= x) r++;
        while (r * (r + 1) / 2 > x) r--;
        bmB = r;
        bnB = x - r * (r + 1) / 2;
    } else {
        bmB = blockIdx.y;
        bnB = blockIdx.x;
    }
    const int bm = bmB * 128;
    const int bn = bnB * 128;

    int Keff = K;
    if (CAUSAL == 2) {
        const int cap = (bmB + 1) * 128;
        Keff = (cap < K) ? cap : K;
    }

    // Loader: 256 threads -> 128 rows x 2 halves of 8 bf16 (16B)
    const int lrow = t >> 1;
    const int lhalf = (t & 1) * 8;
    const __nv_bfloat16* gAh = pAh + (long long)(bm + lrow) * lda + lhalf;
    const __nv_bfloat16* gAl = pAl + (long long)(bm + lrow) * lda + lhalf;
    const __nv_bfloat16* gBh = pBh + (long long)(bn + lrow) * ldb + lhalf;
    const __nv_bfloat16* gBl = pBl + (long long)(bn + lrow) * ldb + lhalf;

    const uint32_t smem0 = (uint32_t)__cvta_generic_to_shared(sm);
    const uint32_t ldst = (uint32_t)((lrow * 16 + lhalf) * 2);

    // ldmatrix per-lane offsets (row stride 32B)
    const uint32_t aoff = (uint32_t)((lane & 15) * 32 + (lane >> 4) * 16);
    const int rB = (lane & 7) | ((lane & 16) >> 1);
    const uint32_t boff = (uint32_t)(rB * 32 + (lane & 8) * 2);

    float c[4][4][4];
#pragma unroll
    for (int i = 0; i < 4; i++)
#pragma unroll
        for (int j = 0; j < 4; j++)
#pragma unroll
            for (int r = 0; r < 4; r++) c[i][j][r] = 0.0f;

    const int T = Keff / 16;

    // prefetch stage 0
    {
        uint32_t da = smem0 + ldst;              // buf0, A hi
        cpasync16(da, gAh);
        cpasync16(da + 4096, gAl);               // A lo
        uint32_t db = smem0 + 16384 + ldst;      // buf0, B hi
        cpasync16(db, gBh);
        cpasync16(db + 4096, gBl);
        cp_commit();
    }

    for (int s = 0; s < T; s++) {
        cp_wait0();
        __syncthreads();

        if (s + 1 < T) {
            const int kk = (s + 1) * 16;
            const int buf = (s + 1) & 1;
            uint32_t da = smem0 + (uint32_t)(buf * 8192) + ldst;
            cpasync16(da, gAh + kk);
            cpasync16(da + 4096, gAl + kk);
            uint32_t db = smem0 + 16384 + (uint32_t)(buf * 8192) + ldst;
            cpasync16(db, gBh + kk);
            cpasync16(db + 4096, gBl + kk);
            cp_commit();
        }

        const int buf = s & 1;
        const uint32_t aH = smem0 + (uint32_t)(buf * 8192) + (uint32_t)(warp_m * 2048) + aoff;
        const uint32_t aL = aH + 4096;
        const uint32_t bH = smem0 + 16384 + (uint32_t)(buf * 8192) + (uint32_t)(warp_n * 1024) + boff;
        const uint32_t bL = bH + 4096;

        uint32_t ah[4][4], al_[4][4], bh[2][4], bl[2][4];
#pragma unroll
        for (int mf = 0; mf < 4; mf++) ldsm4(ah[mf], aH + mf * 512);
#pragma unroll
        for (int mf = 0; mf < 4; mf++) ldsm4(al_[mf], aL + mf * 512);
#pragma unroll
        for (int nb = 0; nb < 2; nb++) ldsm4(bh[nb], bH + nb * 512);
#pragma unroll
        for (int nb = 0; nb < 2; nb++) ldsm4(bl[nb], bL + nb * 512);

        // pass 1: Ahi * Bhi
#pragma unroll
        for (int mf = 0; mf < 4; mf++)
#pragma unroll
            for (int nf = 0; nf < 4; nf++)
                mma16816(c[mf][nf], ah[mf], &bh[nf >> 1][(nf & 1) * 2]);
        // pass 2: Ahi * Blo
#pragma unroll
        for (int mf = 0; mf < 4; mf++)
#pragma unroll
            for (int nf = 0; nf < 4; nf++)
                mma16816(c[mf][nf], ah[mf], &bl[nf >> 1][(nf & 1) * 2]);
        // pass 3: Alo * Bhi
#pragma unroll
        for (int mf = 0; mf < 4; mf++)
#pragma unroll
            for (int nf = 0; nf < 4; nf++)
                mma16816(c[mf][nf], al_[mf], &bh[nf >> 1][(nf & 1) * 2]);

        __syncthreads();
    }

    // --- epilogue ---
    const int gq = lane >> 2;
    const int tg = lane & 3;
#pragma unroll
    for (int mf = 0; mf < 4; mf++) {
#pragma unroll
        for (int nf = 0; nf < 4; nf++) {
            const int r0 = bm + warp_m * 64 + mf * 16 + gq;
            const int c0 = bn + warp_n * 32 + nf * 8 + tg * 2;   // even
            float* cc = c[mf][nf];
            if (EPI == 0) {
                *(float2*)&pC[(long long)r0 * ldc + c0] = make_float2(cc[0], cc[1]);
                *(float2*)&pC[(long long)(r0 + 8) * ldc + c0] = make_float2(cc[2], cc[3]);
            } else if (EPI == 1) {
                // analytic causal mask: (col > row) ? -1e9 : 0
                const float mk00 = (c0 > r0) ? -1000000000.0f : 0.0f;
                const float mk01 = (c0 + 1 > r0) ? -1000000000.0f : 0.0f;
                const float mk10 = (c0 > r0 + 8) ? -1000000000.0f : 0.0f;
                const float mk11 = (c0 + 1 > r0 + 8) ? -1000000000.0f : 0.0f;
                *(float2*)&pC[(long long)r0 * ldc + c0] =
                    make_float2(cc[0] * alpha + mk00, cc[1] * alpha + mk01);
                *(float2*)&pC[(long long)(r0 + 8) * ldc + c0] =
                    make_float2(cc[2] * alpha + mk10, cc[3] * alpha + mk11);
            } else if (EPI == 2) { // V^T hi/lo   Vt[((b*NH+h)*NHD+dc)*NS + s]
#pragma unroll
                for (int q = 0; q < 4; q++) {
                    const int m = r0 + (q >> 1) * 8;
                    const int n = c0 + (q & 1);
                    const int b = m >> 11, sdx = m & 2047;
                    const int h = n >> 7, dc = n & 127;
                    const long long idx =
                        (((long long)(b * NH + h)) * NHD + dc) * NS + sdx;
                    __nv_bfloat16 hb, lb;
                    split2(cc[q], hb, lb);
                    Chi[idx] = hb;
                    Clo[idx] = lb;
                }
            } else { // EPI 3/4: RoPE on (even,odd) pair; 3 also writes fp32
                const int d2 = (c0 & (NHD - 1)) >> 1;
                const int s0 = r0 & (NS - 1);
                const int s1 = (r0 + 8) & (NS - 1);
                const float cv0 = cosT[s0 * (NHD / 2) + d2];
                const float sn0 = sinT[s0 * (NHD / 2) + d2];
                const float cv1 = cosT[s1 * (NHD / 2) + d2];
                const float sn1 = sinT[s1 * (NHD / 2) + d2];
                const float q0 = cc[0] * cv0 - cc[1] * sn0;
                const float q1 = cc[0] * sn0 + cc[1] * cv0;
                const float q2 = cc[2] * cv1 - cc[3] * sn1;
                const float q3 = cc[2] * sn1 + cc[3] * cv1;
                if (EPI == 3) {
                    *(float2*)&pC[(long long)r0 * ldc + c0] = make_float2(q0, q1);
                    *(float2*)&pC[(long long)(r0 + 8) * ldc + c0] = make_float2(q2, q3);
                }
                __nv_bfloat16 hb, lb;
                const long long o0 = (long long)r0 * ldc + c0;
                const long long o1 = (long long)(r0 + 8) * ldc + c0;
                split2(q0, hb, lb); Chi[o0] = hb;     Clo[o0] = lb;
                split2(q1, hb, lb); Chi[o0 + 1] = hb; Clo[o0 + 1] = lb;
                split2(q2, hb, lb); Chi[o1] = hb;     Clo[o1] = lb;
                split2(q3, hb, lb); Chi[o1 + 1] = hb; Clo[o1 + 1] = lb;
            }
        }
    }
}

// ---------------------------------------------------------------------------
// Elementwise fp32 -> bf16 hi/lo split
// ---------------------------------------------------------------------------
__global__ void split_kernel(const float* __restrict__ src,
                             __nv_bfloat16* __restrict__ h,
                             __nv_bfloat16* __restrict__ l, long long n)
{
    long long i = ((long long)blockIdx.x * blockDim.x + threadIdx.x) * 4;
    if (i >= n) return;
    float4 v = *(const float4*)(src + i);
    __nv_bfloat16 hh[4], ll[4];
    split2(v.x, hh[0], ll[0]);
    split2(v.y, hh[1], ll[1]);
    split2(v.z, hh[2], ll[2]);
    split2(v.w, hh[3], ll[3]);
#pragma unroll
    for (int k = 0; k < 4; k++) { h[i + k] = hh[k]; l[i + k] = ll[k]; }
}

// ---------------------------------------------------------------------------
// Weight transpose + split: Wt[n][k] = W[k][n]
// ---------------------------------------------------------------------------
__global__ void wsplit_t_kernel(const float* __restrict__ W,
                                __nv_bfloat16* __restrict__ Th,
                                __nv_bfloat16* __restrict__ Tl)
{
    __shared__ float tile[32][33];
    const int n0 = blockIdx.x * 32, k0 = blockIdx.y * 32;
    const int tx = threadIdx.x, ty = threadIdx.y;
#pragma unroll
    for (int i = 0; i < 4; i++)
        tile[ty + 8 * i][tx] = W[(long long)(k0 + ty + 8 * i) * ND + n0 + tx];
    __syncthreads();
#pragma unroll
    for (int i = 0; i < 4; i++) {
        float v = tile[tx][ty + 8 * i];
        long long o = (long long)(n0 + ty + 8 * i) * ND + k0 + tx;
        __nv_bfloat16 hb, lb;
        split2(v, hb, lb);
        Th[o] = hb;
        Tl[o] = lb;
    }
}

// ---------------------------------------------------------------------------
// Adapter projections (tiny fp32)
// ---------------------------------------------------------------------------
__global__ void adapter_gemm_kernel(const float* __restrict__ adapter,
                                    const float* __restrict__ Wk,
                                    const float* __restrict__ Wv,
                                    float* __restrict__ ak,
                                    float* __restrict__ av)
{
    const int n = blockIdx.x * 256 + threadIdx.x;
    __shared__ float a_sh[NAL][64];
    float accK[NAL], accV[NAL];
#pragma unroll
    for (int r = 0; r < NAL; r++) { accK[r] = 0.f; accV[r] = 0.f; }

    for (int k0 = 0; k0 < ND; k0 += 64) {
        for (int idx = threadIdx.x; idx < NAL * 64; idx += 256) {
            int r = idx / 64, cix = idx % 64;
            a_sh[r][cix] = adapter[r * ND + k0 + cix];
        }
        __syncthreads();
        for (int kc = 0; kc < 64; kc++) {
            float bk = Wk[(long long)(k0 + kc) * ND + n];
            float bv = Wv[(long long)(k0 + kc) * ND + n];
#pragma unroll
            for (int r = 0; r < NAL; r++) {
                accK[r] = fmaf(a_sh[r][kc], bk, accK[r]);
                accV[r] = fmaf(a_sh[r][kc], bv, accV[r]);
            }
        }
        __syncthreads();
    }
#pragma unroll
    for (int r = 0; r < NAL; r++) {
        ak[r * ND + n] = accK[r];
        av[r * ND + n] = accV[r];
    }
}

// ---------------------------------------------------------------------------
// Row softmax -> bf16 hi/lo P (causal: only valid prefix of each row).
// ---------------------------------------------------------------------------
__global__ void softmax_rows_kernel(const float* __restrict__ sc,
                                    __nv_bfloat16* __restrict__ ph,
                                    __nv_bfloat16* __restrict__ pl)
{
    long long row = blockIdx.x;
    const int rq = (int)(row & (NS - 1));
    const int nv = ((rq >> 7) + 1) << 7;
    const float* p = sc + row * (long long)NS;
    const int t = threadIdx.x;

    float v[8];
#pragma unroll
    for (int i = 0; i < 8; i++) {
        const int col = t + i * 256;
        v[i] = (col < nv) ? p[col] : -1e30f;
    }

    float m = -1e30f;
#pragma unroll
    for (int i = 0; i < 8; i++) m = fmaxf(m, v[i]);

    __shared__ float red[256];
    red[t] = m;
    __syncthreads();
    for (int s = 128; s > 0; s >>= 1) {
        if (t < s) red[t] = fmaxf(red[t], red[t + s]);
        __syncthreads();
    }
    m = red[0];
    __syncthreads();

    float sum = 0.f;
#pragma unroll
    for (int i = 0; i < 8; i++) {
        v[i] = __expf(v[i] - m);
        sum += v[i];
    }
    red[t] = sum;
    __syncthreads();
    for (int s = 128; s > 0; s >>= 1) {
        if (t < s) red[t] += red[t + s];
        __syncthreads();
    }
    const float inv = 1.0f / red[0];

    long long base = row * (long long)NS;
#pragma unroll
    for (int i = 0; i < 8; i++) {
        const int col = t + i * 256;
        if (col < nv) {
            float pv = v[i] * inv;
            __nv_bfloat16 hb, lb;
            split2(pv, hb, lb);
            ph[base + col] = hb;
            pl[base + col] = lb;
        }
    }
}

// ---------------------------------------------------------------------------
// Adapter attention add (gated), fp32; writes final AO as bf16 hi/lo split.
// ---------------------------------------------------------------------------
__global__ void adapter_attn_kernel(const float* __restrict__ AO,
                                    const float* __restrict__ Q,
                                    const float* __restrict__ ak,
                                    const float* __restrict__ av,
                                    const float* __restrict__ gate,
                                    __nv_bfloat16* __restrict__ AOh,
                                    __nv_bfloat16* __restrict__ AOl)
{
    const int h = blockIdx.y;
    const int b = blockIdx.z;
    const int lane = threadIdx.x & 31;
    const int w = threadIdx.x >> 5;
    const int q = blockIdx.x * 8 + w;
    const float inv_sqrt = 0.08838834764831845f;

    const float* qp = Q + (((long long)(b * NS + q)) * NH + h) * NHD;
    float qv[4];
#pragma unroll
    for (int i = 0; i < 4; i++) qv[i] = qp[lane + 32 * i];

    float sc[NAL];
#pragma unroll
    for (int j = 0; j < NAL; j++) {
        const float* akp = ak + j * ND + h * NHD;
        float s = 0.f;
#pragma unroll
        for (int i = 0; i < 4; i++) s = fmaf(qv[i], akp[lane + 32 * i], s);
#pragma unroll
        for (int off = 16; off > 0; off >>= 1)
            s += __shfl_xor_sync(0xFFFFFFFFu, s, off);
        sc[j] = s * inv_sqrt;
    }

    float m = sc[0];
#pragma unroll
    for (int j = 1; j < NAL; j++) m = fmaxf(m, sc[j]);
    float sum = 0.f;
#pragma unroll
    for (int j = 0; j < NAL; j++) {
        sc[j] = __expf(sc[j] - m);
        sum += sc[j];
    }
    const float g = gate[h] / sum;

    float o[4] = {0.f, 0.f, 0.f, 0.f};
#pragma unroll
    for (int j = 0; j < NAL; j++) {
        const float* avp = av + j * ND + h * NHD;
#pragma unroll
        for (int i = 0; i < 4; i++) o[i] = fmaf(sc[j], avp[lane + 32 * i], o[i]);
    }

    const long long base = (((long long)(b * NS + q)) * NH + h) * NHD;
#pragma unroll
    for (int i = 0; i < 4; i++) {
        float tot = AO[base + lane + 32 * i] + g * o[i];
        __nv_bfloat16 hb, lb;
        split2(tot, hb, lb);
        AOh[base + lane + 32 * i] = hb;
        AOl[base + lane + 32 * i] = lb;
    }
}

// ---------------------------------------------------------------------------
// Launch sequence
// ---------------------------------------------------------------------------
extern "C" void kernel_launch(void* const* d_in, const int* in_sizes, int n_in,
                              void* d_out, int out_size)
{
    const float* x       = (const float*)d_in[0];
    const float* cosT    = (const float*)d_in[1];
    const float* sinT    = (const float*)d_in[2];
    const float* wq      = (const float*)d_in[4];
    const float* wk      = (const float*)d_in[5];
    const float* wv      = (const float*)d_in[6];
    const float* wo      = (const float*)d_in[7];
    const float* gate    = (const float*)d_in[8];
    const float* adapter = (const float*)d_in[9];
    float* out = (float*)d_out;

    float *Qp, *AOp, *Sc, *akp, *avp;
    __nv_bfloat16 *xh, *xl, *Qh, *Ql, *Kh, *Kl, *Vth, *Vtl, *Ph, *Pl, *AOh, *AOl;
    __nv_bfloat16 *wqh, *wql, *wkh, *wkl, *wvh, *wvl, *woh, *wol;
    cudaGetSymbolAddress((void**)&Qp, g_Q);
    cudaGetSymbolAddress((void**)&AOp, g_AO);
    cudaGetSymbolAddress((void**)&Sc, g_scores);
    cudaGetSymbolAddress((void**)&akp, g_ak);
    cudaGetSymbolAddress((void**)&avp, g_av);
    cudaGetSymbolAddress((void**)&xh, g_xh);
    cudaGetSymbolAddress((void**)&xl, g_xl);
    cudaGetSymbolAddress((void**)&Qh, g_Qh);
    cudaGetSymbolAddress((void**)&Ql, g_Ql);
    cudaGetSymbolAddress((void**)&Kh, g_Kh);
    cudaGetSymbolAddress((void**)&Kl, g_Kl);
    cudaGetSymbolAddress((void**)&Vth, g_Vth);
    cudaGetSymbolAddress((void**)&Vtl, g_Vtl);
    cudaGetSymbolAddress((void**)&Ph, g_Ph);
    cudaGetSymbolAddress((void**)&Pl, g_Pl);
    cudaGetSymbolAddress((void**)&AOh, g_AOh);
    cudaGetSymbolAddress((void**)&AOl, g_AOl);
    cudaGetSymbolAddress((void**)&wqh, g_wqh);
    cudaGetSymbolAddress((void**)&wql, g_wql);
    cudaGetSymbolAddress((void**)&wkh, g_wkh);
    cudaGetSymbolAddress((void**)&wkl, g_wkl);
    cudaGetSymbolAddress((void**)&wvh, g_wvh);
    cudaGetSymbolAddress((void**)&wvl, g_wvl);
    cudaGetSymbolAddress((void**)&woh, g_woh);
    cudaGetSymbolAddress((void**)&wol, g_wol);

    const float inv_sqrt = 0.08838834764831845f;
    const long long NTOK = (long long)NB * NS;          // 4096
    const long long NELT = NTOK * ND;                   // 16M
    dim3 blk(256);

    // 0. Split x; transpose+split weights
    split_kernel<<<(unsigned)(NELT / 1024), 256>>>(x, xh, xl, NELT);
    {
        dim3 g(ND / 32, ND / 32), b(32, 8);
        wsplit_t_kernel<<<g, b>>>(wq, wqh, wql);
        wsplit_t_kernel<<<g, b>>>(wk, wkh, wkl);
        wsplit_t_kernel<<<g, b>>>(wv, wvh, wvl);
        wsplit_t_kernel<<<g, b>>>(wo, woh, wol);
    }

    // 1-3. Projections (M=4096, N=4096, K=4096); RoPE fused for Q and K.
    {
        dim3 g(ND / 128, (unsigned)(NTOK / 128), 1);
        mma_gemm<3, 0><<<g, blk>>>(xh, xl, wqh, wql, Qp, ND, ND, ND, ND, 1,
                                   0, 0, 0, 0, 0, 0, 1.f, cosT, sinT, Qh, Ql);
        mma_gemm<4, 0><<<g, blk>>>(xh, xl, wkh, wkl, nullptr, ND, ND, ND, ND, 1,
                                   0, 0, 0, 0, 0, 0, 1.f, cosT, sinT, Kh, Kl);
        mma_gemm<2, 0><<<g, blk>>>(xh, xl, wvh, wvl, nullptr, ND, ND, ND, ND, 1,
                                   0, 0, 0, 0, 0, 0, 1.f, nullptr, nullptr, Vth, Vtl);
    }

    // 4. Adapter projections
    adapter_gemm_kernel<<<ND / 256, 256>>>(adapter, wk, wv, akp, avp);

    // 5. Scores = Q K^T * inv_sqrt + analytic causal mask — lower-tri blocks.
    {
        dim3 g(136, 1, NB * NH);
        mma_gemm<1, 1><<<g, blk>>>(
            Qh, Ql, Kh, Kl, Sc, NHD, ND, ND, NS, NH,
            (long long)NS * ND, (long long)NHD,
            (long long)NS * ND, (long long)NHD,
            (long long)NH * NS * NS, (long long)NS * NS,
            inv_sqrt, nullptr, nullptr, nullptr, nullptr);
    }

    // 6. Softmax (causal prefix) -> bf16 hi/lo P
    softmax_rows_kernel<<<NB * NH * NS, 256>>>(Sc, Ph, Pl);

    // 7. AO = P @ V  (per (b,h): M=2048, N=128; K capped causally per q-block)
    {
        dim3 g(NHD / 128, NS / 128, NB * NH);
        mma_gemm<0, 2><<<g, blk>>>(
            Ph, Pl, Vth, Vtl, AOp, NS, NS, NS, ND, NH,
            (long long)NH * NS * NS, (long long)NS * NS,
            (long long)NH * NHD * NS, (long long)NHD * NS,
            (long long)NS * ND, (long long)NHD,
            1.f, nullptr, nullptr, nullptr, nullptr);
    }

    // 8. Adapter attention add -> writes AOh/AOl directly
    adapter_attn_kernel<<<dim3(NS / 8, NH, NB), 256>>>(
        AOp, Qp, akp, avp, gate, AOh, AOl);

    // 9. out = AO @ wo
    {
        dim3 g(ND / 128, (unsigned)(NTOK / 128), 1);
        mma_gemm<0, 0><<<g, blk>>>(AOh, AOl, woh, wol, out, ND, ND, ND, ND, 1,
                                   0, 0, 0, 0, 0, 0, 1.f, nullptr, nullptr,
                                   nullptr, nullptr);
    }
}